// round 4
// baseline (speedup 1.0000x reference)
#include <cuda_runtime.h>
#include <math.h>

#define N_NODES 100000
#define E_EDGES 3200000
#define TOT (E_EDGES + N_NODES)

// ---------------- scratch (device globals; allocation-free) ----------------
__device__ __align__(16) float g_h1[N_NODES * 16];      // layer1 features h = x@W1
__device__ float g_asrc1[N_NODES];
__device__ float g_adst1[N_NODES];
__device__ float g_m1[N_NODES];
__device__ float g_denom1[N_NODES];
__device__ __align__(16) float g_numer1[N_NODES * 16];
__device__ float g_e[TOT];                              // per-edge logits (reused both layers)
__device__ __align__(16) float g_h2[N_NODES * 12];      // layer2 features, padded 10->12
__device__ float g_asrc2[N_NODES];
__device__ float g_adst2[N_NODES];
__device__ float g_m2[N_NODES];
__device__ float g_denom2[N_NODES];
__device__ __align__(16) float g_numer2[N_NODES * 12];

// ---------------- helpers ----------------
__device__ __forceinline__ void atomicMaxF(float* addr, float v) {
    // order-safe float max: signed-int max for v>=0, unsigned-int min for v<0
    if (v >= 0.0f) atomicMax((int*)addr, __float_as_int(v));
    else           atomicMin((unsigned int*)addr, __float_as_uint(v));
}

__device__ __forceinline__ void red_add_f(float* p, float v) {
    asm volatile("red.global.add.f32 [%0], %1;" :: "l"(p), "f"(v) : "memory");
}

__device__ __forceinline__ void red_add_v4(float* p, float a, float b, float c, float d) {
    asm volatile("red.global.add.v4.f32 [%0], {%1, %2, %3, %4};"
                 :: "l"(p), "f"(a), "f"(b), "f"(c), "f"(d) : "memory");
}

// ---------------- kernels ----------------

// init layer-1 accumulators
__global__ void k_init1(int N) {
    int t = blockIdx.x * blockDim.x + threadIdx.x;
    if (t < N * 16) g_numer1[t] = 0.0f;
    if (t < N) { g_m1[t] = -INFINITY; g_denom1[t] = 0.0f; }
}

// h1 = x @ W1 ; asrc1 = h1@a1s ; adst1 = h1@a1d.  One warp per node.
__global__ void k_node1(const float* __restrict__ x, const float* __restrict__ W1,
                        const float* __restrict__ a1s, const float* __restrict__ a1d, int N) {
    __shared__ float sWT[16 * 128];   // transposed: sWT[f*128 + k] = W1[k*16 + f]
    for (int i = threadIdx.x; i < 2048; i += blockDim.x) {
        int k = i >> 4, f = i & 15;
        sWT[f * 128 + k] = W1[i];
    }
    __syncthreads();
    int node = blockIdx.x * (blockDim.x >> 5) + (threadIdx.x >> 5);
    int lane = threadIdx.x & 31;
    if (node >= N) return;
    float4 v = __ldg((const float4*)(x + (size_t)node * 128) + lane);
    float hout[16];
#pragma unroll
    for (int f = 0; f < 16; f++) {
        float4 wv = *((const float4*)(sWT + f * 128) + lane);
        float p = v.x * wv.x + v.y * wv.y + v.z * wv.z + v.w * wv.w;
#pragma unroll
        for (int off = 16; off; off >>= 1) p += __shfl_xor_sync(0xffffffffu, p, off);
        hout[f] = p;
    }
    if (lane < 16) g_h1[(size_t)node * 16 + lane] = hout[lane];
    if (lane == 0) {
        float s = 0.0f, d = 0.0f;
#pragma unroll
        for (int f = 0; f < 16; f++) { s += hout[f] * __ldg(a1s + f); d += hout[f] * __ldg(a1d + f); }
        g_asrc1[node] = s; g_adst1[node] = d;
    }
}

// edge pass 1: e = leaky_relu(asrc[s]+adst[d]); segment max over dst.
// LAYER selects which device globals to use (NEVER pass device globals from host!)
template <int LAYER>
__global__ void k_edge(const int* __restrict__ ei, int E, int total) {
    int k = blockIdx.x * blockDim.x + threadIdx.x;
    if (k >= total) return;
    int s, d;
    if (k < E) { s = __ldg(ei + k); d = __ldg(ei + E + k); }
    else       { s = d = k - E; }
    const float* asrc = (LAYER == 1) ? g_asrc1 : g_asrc2;
    const float* adst = (LAYER == 1) ? g_adst1 : g_adst2;
    float*       m    = (LAYER == 1) ? g_m1    : g_m2;
    float e = __ldg(asrc + s) + __ldg(adst + d);
    e = (e > 0.0f) ? e : 0.2f * e;
    g_e[k] = e;
    atomicMaxF(m + d, e);
}

// edge pass 2 (layer 1, F=16): w = exp(e - m[d]); numer[d] += w*h[s]; denom[d] += w
__global__ void k_agg1(const int* __restrict__ ei, int E, int total) {
    int k = blockIdx.x * blockDim.x + threadIdx.x;
    if (k >= total) return;
    int s, d;
    if (k < E) { s = __ldg(ei + k); d = __ldg(ei + E + k); }
    else       { s = d = k - E; }
    float w = __expf(g_e[k] - __ldg(g_m1 + d));
    red_add_f(g_denom1 + d, w);
    const float4* hp = (const float4*)(g_h1 + (size_t)s * 16);
    float4 a = __ldg(hp + 0), b = __ldg(hp + 1), c = __ldg(hp + 2), e4 = __ldg(hp + 3);
    float* np = g_numer1 + (size_t)d * 16;
    red_add_v4(np + 0,  w * a.x,  w * a.y,  w * a.z,  w * a.w);
    red_add_v4(np + 4,  w * b.x,  w * b.y,  w * b.z,  w * b.w);
    red_add_v4(np + 8,  w * c.x,  w * c.y,  w * c.z,  w * c.w);
    red_add_v4(np + 12, w * e4.x, w * e4.y, w * e4.z, w * e4.w);
}

// finalize layer1, compute layer2 features + attention scalars, init layer2 accumulators
__global__ void k_mid(const float* __restrict__ b1, const float* __restrict__ W2,
                      const float* __restrict__ a2s, const float* __restrict__ a2d, int N) {
    int i = blockIdx.x * blockDim.x + threadIdx.x;
    if (i >= N) return;
    float inv = 1.0f / g_denom1[i];
    float g[16];
#pragma unroll
    for (int f = 0; f < 16; f++) {
        float v = g_numer1[(size_t)i * 16 + f] * inv + __ldg(b1 + f);
        g[f] = fmaxf(v, 0.0f);   // ReLU between GAT layers
    }
    float h[10];
#pragma unroll
    for (int c = 0; c < 10; c++) h[c] = 0.0f;
#pragma unroll
    for (int f = 0; f < 16; f++) {
        float gf = g[f];
#pragma unroll
        for (int c = 0; c < 10; c++) h[c] += gf * __ldg(W2 + f * 10 + c);
    }
    float s = 0.0f, d = 0.0f;
    float* hp = g_h2 + (size_t)i * 12;
#pragma unroll
    for (int c = 0; c < 10; c++) {
        s += h[c] * __ldg(a2s + c);
        d += h[c] * __ldg(a2d + c);
        hp[c] = h[c];
    }
    hp[10] = 0.0f; hp[11] = 0.0f;
    g_asrc2[i] = s; g_adst2[i] = d;
    g_m2[i] = -INFINITY; g_denom2[i] = 0.0f;
    float* q = g_numer2 + (size_t)i * 12;
#pragma unroll
    for (int j = 0; j < 12; j++) q[j] = 0.0f;
}

// edge pass 2 (layer 2, F=10 padded to 12)
__global__ void k_agg2(const int* __restrict__ ei, int E, int total) {
    int k = blockIdx.x * blockDim.x + threadIdx.x;
    if (k >= total) return;
    int s, d;
    if (k < E) { s = __ldg(ei + k); d = __ldg(ei + E + k); }
    else       { s = d = k - E; }
    float w = __expf(g_e[k] - __ldg(g_m2 + d));
    red_add_f(g_denom2 + d, w);
    const float4* hp = (const float4*)(g_h2 + (size_t)s * 12);
    float4 a = __ldg(hp + 0), b = __ldg(hp + 1), c = __ldg(hp + 2);
    float* np = g_numer2 + (size_t)d * 12;
    red_add_v4(np + 0, w * a.x, w * a.y, w * a.z, w * a.w);
    red_add_v4(np + 4, w * b.x, w * b.y, w * b.z, w * b.w);
    red_add_v4(np + 8, w * c.x, w * c.y, 0.0f, 0.0f);
}

// finalize layer2 + MLP head -> out[N]
__global__ void k_final(const float* __restrict__ b2,
                        const float* __restrict__ Wl1, const float* __restrict__ bl1,
                        const float* __restrict__ Wl2, const float* __restrict__ bl2,
                        float* __restrict__ out, int N) {
    int i = blockIdx.x * blockDim.x + threadIdx.x;
    if (i >= N) return;
    float inv = 1.0f / g_denom2[i];
    float a[10];
#pragma unroll
    for (int c = 0; c < 10; c++)
        a[c] = g_numer2[(size_t)i * 12 + c] * inv + __ldg(b2 + c);
    float z[10];
#pragma unroll
    for (int c = 0; c < 10; c++) z[c] = __ldg(bl1 + c);
#pragma unroll
    for (int f = 0; f < 10; f++) {
        float af = a[f];
#pragma unroll
        for (int c = 0; c < 10; c++) z[c] += af * __ldg(Wl1 + f * 10 + c);
    }
    float o = __ldg(bl2);
#pragma unroll
    for (int c = 0; c < 10; c++) o += fmaxf(z[c], 0.0f) * __ldg(Wl2 + c);
    out[i] = o;
}

// ---------------- launch ----------------
extern "C" void kernel_launch(void* const* d_in, const int* in_sizes, int n_in,
                              void* d_out, int out_size) {
    const float* x   = (const float*)d_in[0];
    const int*   ei  = (const int*)d_in[1];      // int32 (JAX x64 disabled downcasts int64)
    const float* W1  = (const float*)d_in[2];
    const float* a1s = (const float*)d_in[3];
    const float* a1d = (const float*)d_in[4];
    const float* b1  = (const float*)d_in[5];
    const float* W2  = (const float*)d_in[6];
    const float* a2s = (const float*)d_in[7];
    const float* a2d = (const float*)d_in[8];
    const float* b2  = (const float*)d_in[9];
    const float* Wl1 = (const float*)d_in[10];
    const float* bl1 = (const float*)d_in[11];
    const float* Wl2 = (const float*)d_in[12];
    const float* bl2 = (const float*)d_in[13];
    float* out = (float*)d_out;

    int N = in_sizes[0] / 128;
    int E = in_sizes[1] / 2;
    int total = E + N;

    const int B = 256;
    k_init1<<<(N * 16 + B - 1) / B, B>>>(N);
    k_node1<<<(N + 7) / 8, B>>>(x, W1, a1s, a1d, N);          // 8 warps/block
    k_edge<1><<<(total + B - 1) / B, B>>>(ei, E, total);
    k_agg1 <<<(total + B - 1) / B, B>>>(ei, E, total);
    k_mid  <<<(N + B - 1) / B, B>>>(b1, W2, a2s, a2d, N);
    k_edge<2><<<(total + B - 1) / B, B>>>(ei, E, total);
    k_agg2 <<<(total + B - 1) / B, B>>>(ei, E, total);
    k_final<<<(N + B - 1) / B, B>>>(b2, Wl1, bl1, Wl2, bl2, out, N);
}

// round 5
// speedup vs baseline: 1.1387x; 1.1387x over previous
#include <cuda_runtime.h>
#include <math.h>

#define N_NODES 100000
#define E_EDGES 3200000
#define TOT (E_EDGES + N_NODES)
#define NBLK ((N_NODES + 255) / 256)   // 391 scan blocks

// ---------------- scratch (device globals; allocation-free) ----------------
__device__ __align__(16) float g_h1[N_NODES * 16];    // layer1 features h = x@W1
__device__ __align__(16) float g_o1[N_NODES * 16];    // layer1 attention output
__device__ __align__(16) float g_h2[N_NODES * 12];    // layer2 features (pad 10->12)
__device__ __align__(16) float g_o2[N_NODES * 12];    // layer2 attention output
__device__ float g_asrc1[N_NODES];
__device__ float g_adst1[N_NODES];
__device__ float g_asrc2[N_NODES];
__device__ float g_adst2[N_NODES];
__device__ int   g_cnt[N_NODES];        // per-dst degree histogram
__device__ int   g_rowstart[N_NODES + 1];
__device__ int   g_cursor[N_NODES];     // scatter cursors
__device__ int   g_bsum[512];           // scan block sums
__device__ int   g_csr[TOT];            // src node per edge, grouped by dst

// ---------------- CSR build ----------------
__global__ void k_zero(int N) {
    int i = blockIdx.x * blockDim.x + threadIdx.x;
    if (i < N) g_cnt[i] = 0;
}

__global__ void k_hist(const int* __restrict__ ei, int E, int total) {
    int k = blockIdx.x * blockDim.x + threadIdx.x;
    if (k >= total) return;
    int d = (k < E) ? __ldg(ei + E + k) : (k - E);
    atomicAdd(g_cnt + d, 1);
}

// per-block exclusive scan of g_cnt -> partial g_rowstart, block totals g_bsum
__global__ void k_scan1(int N) {
    __shared__ int s[256];
    int tid = threadIdx.x;
    int i = blockIdx.x * 256 + tid;
    int v = (i < N) ? g_cnt[i] : 0;
    s[tid] = v;
    __syncthreads();
#pragma unroll
    for (int o = 1; o < 256; o <<= 1) {
        int t = (tid >= o) ? s[tid - o] : 0;
        __syncthreads();
        s[tid] += t;
        __syncthreads();
    }
    if (i < N) g_rowstart[i] = s[tid] - v;           // exclusive within block
    if (tid == 255) g_bsum[blockIdx.x] = s[255];     // block total
}

// single-block exclusive scan of block sums (NBLK <= 512)
__global__ void k_scan2(int nb) {
    __shared__ int s[512];
    int tid = threadIdx.x;
    int v = (tid < nb) ? g_bsum[tid] : 0;
    s[tid] = v;
    __syncthreads();
#pragma unroll
    for (int o = 1; o < 512; o <<= 1) {
        int t = (tid >= o) ? s[tid - o] : 0;
        __syncthreads();
        s[tid] += t;
        __syncthreads();
    }
    if (tid < nb) g_bsum[tid] = s[tid] - v;          // exclusive
}

__global__ void k_scan3(int N, int total) {
    int i = blockIdx.x * blockDim.x + threadIdx.x;
    if (i < N) {
        int r = g_rowstart[i] + g_bsum[i >> 8];
        g_rowstart[i] = r;
        g_cursor[i] = r;
    }
    if (i == 0) g_rowstart[N] = total;
}

__global__ void k_scatter(const int* __restrict__ ei, int E, int total) {
    int k = blockIdx.x * blockDim.x + threadIdx.x;
    if (k >= total) return;
    int s, d;
    if (k < E) { s = __ldg(ei + k); d = __ldg(ei + E + k); }
    else       { s = d = k - E; }
    int pos = atomicAdd(g_cursor + d, 1);
    g_csr[pos] = s;
}

// ---------------- node / layer kernels ----------------

// h1 = x @ W1 ; asrc1 = h1@a1s ; adst1 = h1@a1d.  One warp per node.
__global__ void k_node1(const float* __restrict__ x, const float* __restrict__ W1,
                        const float* __restrict__ a1s, const float* __restrict__ a1d, int N) {
    __shared__ float sWT[16 * 128];   // transposed: sWT[f*128 + k] = W1[k*16 + f]
    for (int i = threadIdx.x; i < 2048; i += blockDim.x) {
        int k = i >> 4, f = i & 15;
        sWT[f * 128 + k] = W1[i];
    }
    __syncthreads();
    int node = blockIdx.x * (blockDim.x >> 5) + (threadIdx.x >> 5);
    int lane = threadIdx.x & 31;
    if (node >= N) return;
    float4 v = __ldg((const float4*)(x + (size_t)node * 128) + lane);
    float hout[16];
#pragma unroll
    for (int f = 0; f < 16; f++) {
        float4 wv = *((const float4*)(sWT + f * 128) + lane);
        float p = v.x * wv.x + v.y * wv.y + v.z * wv.z + v.w * wv.w;
#pragma unroll
        for (int off = 16; off; off >>= 1) p += __shfl_xor_sync(0xffffffffu, p, off);
        hout[f] = p;
    }
    if (lane < 16) g_h1[(size_t)node * 16 + lane] = hout[lane];
    if (lane == 0) {
        float s = 0.0f, d = 0.0f;
#pragma unroll
        for (int f = 0; f < 16; f++) { s += hout[f] * __ldg(a1s + f); d += hout[f] * __ldg(a1d + f); }
        g_asrc1[node] = s; g_adst1[node] = d;
    }
}

// gather-based softmax aggregation, one warp per dst node.  LAYER picks globals.
template <int LAYER>
__global__ void k_agg(int N) {
    int node = (blockIdx.x * blockDim.x + threadIdx.x) >> 5;
    int lane = threadIdx.x & 31;
    if (node >= N) return;
    int start = __ldg(g_rowstart + node);
    int end   = __ldg(g_rowstart + node + 1);
    const float* asrc = (LAYER == 1) ? g_asrc1 : g_asrc2;
    float ad = (LAYER == 1) ? g_adst1[node] : g_adst2[node];

    // pass 1: segment max
    float m = -INFINITY;
    for (int j = start + lane; j < end; j += 32) {
        int s = __ldg(g_csr + j);
        float e = __ldg(asrc + s) + ad;
        e = (e > 0.0f) ? e : 0.2f * e;
        m = fmaxf(m, e);
    }
#pragma unroll
    for (int o = 16; o; o >>= 1) m = fmaxf(m, __shfl_xor_sync(0xffffffffu, m, o));

    // pass 2: weighted sum (indices/asrc now hot in L1/L2)
    constexpr int F = (LAYER == 1) ? 16 : 12;
    float num[F];
#pragma unroll
    for (int f = 0; f < F; f++) num[f] = 0.0f;
    float den = 0.0f;
    for (int j = start + lane; j < end; j += 32) {
        int s = __ldg(g_csr + j);
        float e = __ldg(asrc + s) + ad;
        e = (e > 0.0f) ? e : 0.2f * e;
        float w = __expf(e - m);
        den += w;
        const float4* hp = (LAYER == 1)
            ? (const float4*)(g_h1 + (size_t)s * 16)
            : (const float4*)(g_h2 + (size_t)s * 12);
#pragma unroll
        for (int q = 0; q < F / 4; q++) {
            float4 hv = __ldg(hp + q);
            num[q * 4 + 0] += w * hv.x;
            num[q * 4 + 1] += w * hv.y;
            num[q * 4 + 2] += w * hv.z;
            num[q * 4 + 3] += w * hv.w;
        }
    }
#pragma unroll
    for (int o = 16; o; o >>= 1) {
        den += __shfl_xor_sync(0xffffffffu, den, o);
#pragma unroll
        for (int f = 0; f < F; f++) num[f] += __shfl_xor_sync(0xffffffffu, num[f], o);
    }
    if (lane == 0) {
        float inv = 1.0f / den;   // den >= self-loop weight > 0
        float* op = (LAYER == 1) ? (g_o1 + (size_t)node * 16) : (g_o2 + (size_t)node * 12);
#pragma unroll
        for (int q = 0; q < F / 4; q++) {
            float4 r;
            r.x = num[q * 4 + 0] * inv; r.y = num[q * 4 + 1] * inv;
            r.z = num[q * 4 + 2] * inv; r.w = num[q * 4 + 3] * inv;
            ((float4*)op)[q] = r;
        }
    }
}

// finalize layer1 (+bias, relu), compute layer2 features + attention scalars
__global__ void k_mid(const float* __restrict__ b1, const float* __restrict__ W2,
                      const float* __restrict__ a2s, const float* __restrict__ a2d, int N) {
    int i = blockIdx.x * blockDim.x + threadIdx.x;
    if (i >= N) return;
    float g[16];
#pragma unroll
    for (int f = 0; f < 16; f++)
        g[f] = fmaxf(g_o1[(size_t)i * 16 + f] + __ldg(b1 + f), 0.0f);
    float h[10];
#pragma unroll
    for (int c = 0; c < 10; c++) h[c] = 0.0f;
#pragma unroll
    for (int f = 0; f < 16; f++) {
        float gf = g[f];
#pragma unroll
        for (int c = 0; c < 10; c++) h[c] += gf * __ldg(W2 + f * 10 + c);
    }
    float s = 0.0f, d = 0.0f;
    float* hp = g_h2 + (size_t)i * 12;
#pragma unroll
    for (int c = 0; c < 10; c++) {
        s += h[c] * __ldg(a2s + c);
        d += h[c] * __ldg(a2d + c);
        hp[c] = h[c];
    }
    hp[10] = 0.0f; hp[11] = 0.0f;
    g_asrc2[i] = s; g_adst2[i] = d;
}

// finalize layer2 + MLP head -> out[N]
__global__ void k_final(const float* __restrict__ b2,
                        const float* __restrict__ Wl1, const float* __restrict__ bl1,
                        const float* __restrict__ Wl2, const float* __restrict__ bl2,
                        float* __restrict__ out, int N) {
    int i = blockIdx.x * blockDim.x + threadIdx.x;
    if (i >= N) return;
    float a[10];
#pragma unroll
    for (int c = 0; c < 10; c++)
        a[c] = g_o2[(size_t)i * 12 + c] + __ldg(b2 + c);
    float z[10];
#pragma unroll
    for (int c = 0; c < 10; c++) z[c] = __ldg(bl1 + c);
#pragma unroll
    for (int f = 0; f < 10; f++) {
        float af = a[f];
#pragma unroll
        for (int c = 0; c < 10; c++) z[c] += af * __ldg(Wl1 + f * 10 + c);
    }
    float o = __ldg(bl2);
#pragma unroll
    for (int c = 0; c < 10; c++) o += fmaxf(z[c], 0.0f) * __ldg(Wl2 + c);
    out[i] = o;
}

// ---------------- launch ----------------
extern "C" void kernel_launch(void* const* d_in, const int* in_sizes, int n_in,
                              void* d_out, int out_size) {
    const float* x   = (const float*)d_in[0];
    const int*   ei  = (const int*)d_in[1];      // int32 (JAX x64 disabled downcasts int64)
    const float* W1  = (const float*)d_in[2];
    const float* a1s = (const float*)d_in[3];
    const float* a1d = (const float*)d_in[4];
    const float* b1  = (const float*)d_in[5];
    const float* W2  = (const float*)d_in[6];
    const float* a2s = (const float*)d_in[7];
    const float* a2d = (const float*)d_in[8];
    const float* b2  = (const float*)d_in[9];
    const float* Wl1 = (const float*)d_in[10];
    const float* bl1 = (const float*)d_in[11];
    const float* Wl2 = (const float*)d_in[12];
    const float* bl2 = (const float*)d_in[13];
    float* out = (float*)d_out;

    int N = in_sizes[0] / 128;
    int E = in_sizes[1] / 2;
    int total = E + N;
    int nb = (N + 255) / 256;

    const int B = 256;
    // CSR build (per-launch, deterministic up to fp-neutral edge order)
    k_zero   <<<nb, B>>>(N);
    k_hist   <<<(total + B - 1) / B, B>>>(ei, E, total);
    k_scan1  <<<nb, B>>>(N);
    k_scan2  <<<1, 512>>>(nb);
    k_scan3  <<<nb, B>>>(N, total);
    k_scatter<<<(total + B - 1) / B, B>>>(ei, E, total);
    // GAT layer 1
    k_node1  <<<(N + 7) / 8, B>>>(x, W1, a1s, a1d, N);
    k_agg<1> <<<(N + 7) / 8, B>>>(N);
    k_mid    <<<(N + B - 1) / B, B>>>(b1, W2, a2s, a2d, N);
    // GAT layer 2
    k_agg<2> <<<(N + 7) / 8, B>>>(N);
    k_final  <<<(N + B - 1) / B, B>>>(b2, Wl1, bl1, Wl2, bl2, out, N);
}

// round 6
// speedup vs baseline: 1.4366x; 1.2616x over previous
#include <cuda_runtime.h>
#include <cuda_fp16.h>
#include <math.h>

#define N_NODES 100000
#define E_EDGES 3200000

// ---------------- scratch (device globals; allocation-free) ----------------
__device__ __align__(16) uint4 g_h1h[N_NODES * 2];   // layer1 h, 16 fp16 = 32B/row
__device__ __align__(16) uint4 g_h2h[N_NODES * 2];   // layer2 h, 10 fp16 + pad
__device__ __align__(16) float g_o1[N_NODES * 16];   // layer1 attention output (fp32)
__device__ __align__(16) float g_o2[N_NODES * 16];   // layer2 attention output (fp32)
__device__ float g_asrc1[N_NODES];
__device__ float g_adst1[N_NODES];
__device__ float g_asrc2[N_NODES];
__device__ float g_adst2[N_NODES];
__device__ int   g_cnt[N_NODES];
__device__ int   g_rowstart[N_NODES + 1];
__device__ int   g_cursor[N_NODES];
__device__ int   g_bsum[512];
__device__ int   g_csr[E_EDGES];        // src per edge, grouped by dst (no self loops)

// ---------------- CSR build ----------------
__global__ void k_zero(int N) {
    int i = blockIdx.x * blockDim.x + threadIdx.x;
    if (i < N) g_cnt[i] = 0;
}

__global__ void k_hist(const int* __restrict__ ei, int E) {
    int k = blockIdx.x * blockDim.x + threadIdx.x;
    if (k < E) atomicAdd(g_cnt + __ldg(ei + E + k), 1);
}

__global__ void k_scan1(int N) {
    __shared__ int s[256];
    int tid = threadIdx.x;
    int i = blockIdx.x * 256 + tid;
    int v = (i < N) ? g_cnt[i] : 0;
    s[tid] = v;
    __syncthreads();
#pragma unroll
    for (int o = 1; o < 256; o <<= 1) {
        int t = (tid >= o) ? s[tid - o] : 0;
        __syncthreads();
        s[tid] += t;
        __syncthreads();
    }
    if (i < N) g_rowstart[i] = s[tid] - v;
    if (tid == 255) g_bsum[blockIdx.x] = s[255];
}

__global__ void k_scan2(int nb) {
    __shared__ int s[512];
    int tid = threadIdx.x;
    int v = (tid < nb) ? g_bsum[tid] : 0;
    s[tid] = v;
    __syncthreads();
#pragma unroll
    for (int o = 1; o < 512; o <<= 1) {
        int t = (tid >= o) ? s[tid - o] : 0;
        __syncthreads();
        s[tid] += t;
        __syncthreads();
    }
    if (tid < nb) g_bsum[tid] = s[tid] - v;
}

__global__ void k_scan3(int N, int E) {
    int i = blockIdx.x * blockDim.x + threadIdx.x;
    if (i < N) {
        int r = g_rowstart[i] + g_bsum[i >> 8];
        g_rowstart[i] = r;
        g_cursor[i] = r;
    }
    if (i == 0) g_rowstart[N] = E;
}

__global__ void k_scatter(const int* __restrict__ ei, int E) {
    int k = blockIdx.x * blockDim.x + threadIdx.x;
    if (k >= E) return;
    int s = __ldg(ei + k), d = __ldg(ei + E + k);
    g_csr[atomicAdd(g_cursor + d, 1)] = s;
}

// ---------------- helpers ----------------
__device__ __forceinline__ unsigned pack2(float a, float b) {
    __half2 h = __floats2half2_rn(a, b);
    return *(unsigned*)&h;
}

__device__ __forceinline__ void acc8(uint4 r, float w, float* acc) {
    float2 p;
    p = __half22float2(*(__half2*)&r.x); acc[0] += w * p.x; acc[1] += w * p.y;
    p = __half22float2(*(__half2*)&r.y); acc[2] += w * p.x; acc[3] += w * p.y;
    p = __half22float2(*(__half2*)&r.z); acc[4] += w * p.x; acc[5] += w * p.y;
    p = __half22float2(*(__half2*)&r.w); acc[6] += w * p.x; acc[7] += w * p.y;
}

// ---------------- node / layer kernels ----------------

// h1 = x @ W1 (fp32 math, fp16 store); asrc1/adst1.  One warp per node.
__global__ void k_node1(const float* __restrict__ x, const float* __restrict__ W1,
                        const float* __restrict__ a1s, const float* __restrict__ a1d, int N) {
    __shared__ float sWT[16 * 128];   // sWT[f*128 + k] = W1[k*16 + f]
    for (int i = threadIdx.x; i < 2048; i += blockDim.x) {
        int k = i >> 4, f = i & 15;
        sWT[f * 128 + k] = W1[i];
    }
    __syncthreads();
    int node = blockIdx.x * (blockDim.x >> 5) + (threadIdx.x >> 5);
    int lane = threadIdx.x & 31;
    if (node >= N) return;
    float4 v = __ldg((const float4*)(x + (size_t)node * 128) + lane);
    float hout[16];
#pragma unroll
    for (int f = 0; f < 16; f++) {
        float4 wv = *((const float4*)(sWT + f * 128) + lane);
        float p = v.x * wv.x + v.y * wv.y + v.z * wv.z + v.w * wv.w;
#pragma unroll
        for (int off = 16; off; off >>= 1) p += __shfl_xor_sync(0xffffffffu, p, off);
        hout[f] = p;
    }
    if (lane == 0) {
        uint4 u0, u1;
        u0.x = pack2(hout[0], hout[1]);   u0.y = pack2(hout[2], hout[3]);
        u0.z = pack2(hout[4], hout[5]);   u0.w = pack2(hout[6], hout[7]);
        u1.x = pack2(hout[8], hout[9]);   u1.y = pack2(hout[10], hout[11]);
        u1.z = pack2(hout[12], hout[13]); u1.w = pack2(hout[14], hout[15]);
        g_h1h[node * 2 + 0] = u0;
        g_h1h[node * 2 + 1] = u1;
        float s = 0.0f, d = 0.0f;
#pragma unroll
        for (int f = 0; f < 16; f++) { s += hout[f] * __ldg(a1s + f); d += hout[f] * __ldg(a1d + f); }
        g_asrc1[node] = s; g_adst1[node] = d;
    }
}

// softmax aggregation (no max subtraction), warp per node, 2 lanes per edge.
template <int LAYER>
__global__ void k_agg(int N) {
    int node = (blockIdx.x * blockDim.x + threadIdx.x) >> 5;
    if (node >= N) return;
    int lane = threadIdx.x & 31;
    int pair = lane >> 1, sub = lane & 1;
    int start = __ldg(g_rowstart + node);
    int end   = __ldg(g_rowstart + node + 1);
    const float* asrc = (LAYER == 1) ? g_asrc1 : g_asrc2;
    const uint4* hrow = (LAYER == 1) ? g_h1h : g_h2h;
    float ad = (LAYER == 1) ? g_adst1[node] : g_adst2[node];

    float acc[8];
#pragma unroll
    for (int f = 0; f < 8; f++) acc[f] = 0.0f;
    float den = 0.0f;

    for (int j = start + pair; j < end; j += 16) {
        int s = __ldg(g_csr + j);
        float e = __ldg(asrc + s) + ad;
        e = (e > 0.0f) ? e : 0.2f * e;
        float w = __expf(e);
        if (sub == 0) den += w;
        uint4 r = __ldg(hrow + s * 2 + sub);
        acc8(r, w, acc);
    }
    if (pair == 0) {   // self loop
        float e = __ldg(asrc + node) + ad;
        e = (e > 0.0f) ? e : 0.2f * e;
        float w = __expf(e);
        if (sub == 0) den += w;
        uint4 r = __ldg(hrow + node * 2 + sub);
        acc8(r, w, acc);
    }

    // reduce: acc across pairs only (keep sub split), den across all lanes
#pragma unroll
    for (int o = 16; o >= 2; o >>= 1) {
#pragma unroll
        for (int f = 0; f < 8; f++) acc[f] += __shfl_xor_sync(0xffffffffu, acc[f], o);
    }
#pragma unroll
    for (int o = 16; o >= 1; o >>= 1) den += __shfl_xor_sync(0xffffffffu, den, o);

    float inv = 1.0f / den;
    if (lane < 2) {
        float* op = ((LAYER == 1) ? g_o1 : g_o2) + (size_t)node * 16 + sub * 8;
        ((float4*)op)[0] = make_float4(acc[0] * inv, acc[1] * inv, acc[2] * inv, acc[3] * inv);
        ((float4*)op)[1] = make_float4(acc[4] * inv, acc[5] * inv, acc[6] * inv, acc[7] * inv);
    }
}

// finalize layer1 (+bias, relu), layer2 features (fp16 rows) + attention scalars
__global__ void k_mid(const float* __restrict__ b1, const float* __restrict__ W2,
                      const float* __restrict__ a2s, const float* __restrict__ a2d, int N) {
    int i = blockIdx.x * blockDim.x + threadIdx.x;
    if (i >= N) return;
    float g[16];
    const float4* op = (const float4*)(g_o1 + (size_t)i * 16);
#pragma unroll
    for (int q = 0; q < 4; q++) {
        float4 v = op[q];
        g[q * 4 + 0] = fmaxf(v.x + __ldg(b1 + q * 4 + 0), 0.0f);
        g[q * 4 + 1] = fmaxf(v.y + __ldg(b1 + q * 4 + 1), 0.0f);
        g[q * 4 + 2] = fmaxf(v.z + __ldg(b1 + q * 4 + 2), 0.0f);
        g[q * 4 + 3] = fmaxf(v.w + __ldg(b1 + q * 4 + 3), 0.0f);
    }
    float h[10];
#pragma unroll
    for (int c = 0; c < 10; c++) h[c] = 0.0f;
#pragma unroll
    for (int f = 0; f < 16; f++) {
        float gf = g[f];
#pragma unroll
        for (int c = 0; c < 10; c++) h[c] += gf * __ldg(W2 + f * 10 + c);
    }
    float s = 0.0f, d = 0.0f;
#pragma unroll
    for (int c = 0; c < 10; c++) { s += h[c] * __ldg(a2s + c); d += h[c] * __ldg(a2d + c); }
    uint4 u0, u1;
    u0.x = pack2(h[0], h[1]); u0.y = pack2(h[2], h[3]);
    u0.z = pack2(h[4], h[5]); u0.w = pack2(h[6], h[7]);
    u1.x = pack2(h[8], h[9]); u1.y = 0u; u1.z = 0u; u1.w = 0u;
    g_h2h[i * 2 + 0] = u0;
    g_h2h[i * 2 + 1] = u1;
    g_asrc2[i] = s; g_adst2[i] = d;
}

// finalize layer2 + MLP head -> out[N]
__global__ void k_final(const float* __restrict__ b2,
                        const float* __restrict__ Wl1, const float* __restrict__ bl1,
                        const float* __restrict__ Wl2, const float* __restrict__ bl2,
                        float* __restrict__ out, int N) {
    int i = blockIdx.x * blockDim.x + threadIdx.x;
    if (i >= N) return;
    float a[10];
#pragma unroll
    for (int c = 0; c < 10; c++)
        a[c] = g_o2[(size_t)i * 16 + c] + __ldg(b2 + c);
    float z[10];
#pragma unroll
    for (int c = 0; c < 10; c++) z[c] = __ldg(bl1 + c);
#pragma unroll
    for (int f = 0; f < 10; f++) {
        float af = a[f];
#pragma unroll
        for (int c = 0; c < 10; c++) z[c] += af * __ldg(Wl1 + f * 10 + c);
    }
    float o = __ldg(bl2);
#pragma unroll
    for (int c = 0; c < 10; c++) o += fmaxf(z[c], 0.0f) * __ldg(Wl2 + c);
    out[i] = o;
}

// ---------------- launch ----------------
extern "C" void kernel_launch(void* const* d_in, const int* in_sizes, int n_in,
                              void* d_out, int out_size) {
    const float* x   = (const float*)d_in[0];
    const int*   ei  = (const int*)d_in[1];      // int32
    const float* W1  = (const float*)d_in[2];
    const float* a1s = (const float*)d_in[3];
    const float* a1d = (const float*)d_in[4];
    const float* b1  = (const float*)d_in[5];
    const float* W2  = (const float*)d_in[6];
    const float* a2s = (const float*)d_in[7];
    const float* a2d = (const float*)d_in[8];
    const float* b2  = (const float*)d_in[9];
    const float* Wl1 = (const float*)d_in[10];
    const float* bl1 = (const float*)d_in[11];
    const float* Wl2 = (const float*)d_in[12];
    const float* bl2 = (const float*)d_in[13];
    float* out = (float*)d_out;

    int N = in_sizes[0] / 128;
    int E = in_sizes[1] / 2;
    int nb = (N + 255) / 256;

    const int B = 256;
    k_zero   <<<nb, B>>>(N);
    k_hist   <<<(E + B - 1) / B, B>>>(ei, E);
    k_scan1  <<<nb, B>>>(N);
    k_scan2  <<<1, 512>>>(nb);
    k_scan3  <<<nb, B>>>(N, E);
    k_scatter<<<(E + B - 1) / B, B>>>(ei, E);
    k_node1  <<<(N + 7) / 8, B>>>(x, W1, a1s, a1d, N);
    k_agg<1> <<<(N + 7) / 8, B>>>(N);
    k_mid    <<<(N + B - 1) / B, B>>>(b1, W2, a2s, a2d, N);
    k_agg<2> <<<(N + 7) / 8, B>>>(N);
    k_final  <<<(N + B - 1) / B, B>>>(b2, Wl1, bl1, Wl2, bl2, out, N);
}